// round 2
// baseline (speedup 1.0000x reference)
#include <cuda_runtime.h>
#include <cuda_bf16.h>

#define SRC_LEN 256
#define TRG_LEN 256
#define BATCH   32
#define HID     512
#define ATT     128

// Scratch for projected activations (device globals; no allocation allowed).
// Layout: [(len_idx * BATCH + b) * ATT + a]
__device__ float g_enc_att[SRC_LEN * BATCH * ATT];
__device__ float g_dec_att[TRG_LEN * BATCH * ATT];

__device__ __forceinline__ float tanh_fast(float x) {
    float y;
    asm("tanh.approx.f32 %0, %1;" : "=f"(y) : "f"(x));
    return y;
}

// ---------------------------------------------------------------------------
// Projection GEMM: C[row][n] = sum_h X[row][h] * W[n][h]  (+ bias if z==1)
// X: 8192 x 512 row-major, W: 128 x 512 row-major, C: 8192 x 128.
// Tiling: BM=64, BN=64, BK=32, 256 threads, 4x4 register tile per thread.
// grid = (rows/64 = 128, ATT/64 = 2, 2 [enc|dec])
// ---------------------------------------------------------------------------
__global__ __launch_bounds__(256) void proj_kernel(
    const float* __restrict__ dec_out,
    const float* __restrict__ enc_outs,
    const float* __restrict__ W_s,
    const float* __restrict__ W_t,
    const float* __restrict__ b_t)
{
    const int z = blockIdx.z;
    const float* __restrict__ X = z ? dec_out : enc_outs;
    const float* __restrict__ W = z ? W_t : W_s;
    float* __restrict__ C = z ? g_dec_att : g_enc_att;

    __shared__ float As[32][64];  // [k][m]
    __shared__ float Bs[32][64];  // [k][n]

    const int tid = threadIdx.x;
    const int tx = tid & 15;       // n-dim thread
    const int ty = tid >> 4;       // m-dim thread
    const int m0 = blockIdx.x * 64;
    const int n0 = blockIdx.y * 64;

    float acc[4][4];
    #pragma unroll
    for (int i = 0; i < 4; i++)
        #pragma unroll
        for (int j = 0; j < 4; j++) acc[i][j] = 0.f;

    for (int k0 = 0; k0 < HID; k0 += 32) {
        // Load A tile (64x32) and B tile (64x32): 512 float4 each, 2 per thread.
        #pragma unroll
        for (int r = 0; r < 2; r++) {
            const int i  = (tid << 1) + r;     // 0..511
            const int m  = i >> 3;             // row within tile
            const int kq = i & 7;              // float4 index within 32-k chunk
            const float4 va = *reinterpret_cast<const float4*>(
                X + (size_t)(m0 + m) * HID + k0 + (kq << 2));
            As[kq * 4 + 0][m] = va.x;
            As[kq * 4 + 1][m] = va.y;
            As[kq * 4 + 2][m] = va.z;
            As[kq * 4 + 3][m] = va.w;
            const float4 vb = *reinterpret_cast<const float4*>(
                W + (size_t)(n0 + m) * HID + k0 + (kq << 2));
            Bs[kq * 4 + 0][m] = vb.x;
            Bs[kq * 4 + 1][m] = vb.y;
            Bs[kq * 4 + 2][m] = vb.z;
            Bs[kq * 4 + 3][m] = vb.w;
        }
        __syncthreads();

        #pragma unroll
        for (int kk = 0; kk < 32; kk++) {
            const float4 av = *reinterpret_cast<const float4*>(&As[kk][ty << 2]);
            const float4 bv = *reinterpret_cast<const float4*>(&Bs[kk][tx << 2]);
            const float a[4] = {av.x, av.y, av.z, av.w};
            const float b[4] = {bv.x, bv.y, bv.z, bv.w};
            #pragma unroll
            for (int i = 0; i < 4; i++)
                #pragma unroll
                for (int j = 0; j < 4; j++)
                    acc[i][j] = fmaf(a[i], b[j], acc[i][j]);
        }
        __syncthreads();
    }

    // Epilogue: optional bias for the dec projection, then float4 stores.
    float bias[4] = {0.f, 0.f, 0.f, 0.f};
    if (z) {
        #pragma unroll
        for (int j = 0; j < 4; j++) bias[j] = b_t[n0 + (tx << 2) + j];
    }
    #pragma unroll
    for (int i = 0; i < 4; i++) {
        float4 o;
        o.x = acc[i][0] + bias[0];
        o.y = acc[i][1] + bias[1];
        o.z = acc[i][2] + bias[2];
        o.w = acc[i][3] + bias[3];
        *reinterpret_cast<float4*>(
            C + (size_t)(m0 + (ty << 2) + i) * ATT + n0 + (tx << 2)) = o;
    }
}

// ---------------------------------------------------------------------------
// Score kernel: out[t][b][s] = sum_a v[a] * tanh(dec_att[t,b,a] + enc_att[s,b,a])
// Tile: 32 t x 32 s per block, one b per block.z. 256 threads, 2x2 per thread.
// SMEM tiles stored transposed [a][row] with +1 pad -> conflict-free inner LDS.
// grid = (SRC/32 = 8, TRG/32 = 8, BATCH = 32)
// ---------------------------------------------------------------------------
__global__ __launch_bounds__(256) void score_kernel(
    const float* __restrict__ v_a,
    float* __restrict__ out)
{
    __shared__ float sh_e[ATT][33];
    __shared__ float sh_d[ATT][33];
    __shared__ float sh_v[ATT];

    const int tid = threadIdx.x;
    const int b = blockIdx.z;
    const int s_base = blockIdx.x * 32;
    const int t_base = blockIdx.y * 32;

    // Cooperative tile load: 32 rows x 128 a, vectorized float4 (1024 per array).
    for (int idx = tid; idx < 32 * 32; idx += 256) {
        const int i  = idx >> 5;      // row within tile
        const int a4 = idx & 31;      // float4 index along a
        const float4 ev = *reinterpret_cast<const float4*>(
            g_enc_att + ((size_t)(s_base + i) * BATCH + b) * ATT + (a4 << 2));
        sh_e[a4 * 4 + 0][i] = ev.x;
        sh_e[a4 * 4 + 1][i] = ev.y;
        sh_e[a4 * 4 + 2][i] = ev.z;
        sh_e[a4 * 4 + 3][i] = ev.w;
        const float4 dv = *reinterpret_cast<const float4*>(
            g_dec_att + ((size_t)(t_base + i) * BATCH + b) * ATT + (a4 << 2));
        sh_d[a4 * 4 + 0][i] = dv.x;
        sh_d[a4 * 4 + 1][i] = dv.y;
        sh_d[a4 * 4 + 2][i] = dv.z;
        sh_d[a4 * 4 + 3][i] = dv.w;
    }
    if (tid < ATT) sh_v[tid] = v_a[tid];
    __syncthreads();

    const int tx = tid & 15;         // s-dim
    const int ty = tid >> 4;         // t-dim
    const int sl = tx << 1;
    const int tl = ty << 1;

    float acc00 = 0.f, acc01 = 0.f, acc10 = 0.f, acc11 = 0.f;

    #pragma unroll 4
    for (int a = 0; a < ATT; a++) {
        const float va = sh_v[a];
        const float e0 = sh_e[a][sl];
        const float e1 = sh_e[a][sl + 1];
        const float d0 = sh_d[a][tl];
        const float d1 = sh_d[a][tl + 1];
        acc00 = fmaf(va, tanh_fast(d0 + e0), acc00);
        acc01 = fmaf(va, tanh_fast(d0 + e1), acc01);
        acc10 = fmaf(va, tanh_fast(d1 + e0), acc10);
        acc11 = fmaf(va, tanh_fast(d1 + e1), acc11);
    }

    const int tg = t_base + tl;
    const int sg = s_base + sl;
    float* o0 = out + ((size_t)tg * BATCH + b) * SRC_LEN + sg;
    float2 r0; r0.x = acc00; r0.y = acc01;
    *reinterpret_cast<float2*>(o0) = r0;
    float* o1 = o0 + (size_t)BATCH * SRC_LEN;   // t+1
    float2 r1; r1.x = acc10; r1.y = acc11;
    *reinterpret_cast<float2*>(o1) = r1;
}

extern "C" void kernel_launch(void* const* d_in, const int* in_sizes, int n_in,
                              void* d_out, int out_size)
{
    const float* dec_out  = (const float*)d_in[0];  // (256, 32, 512)
    const float* enc_outs = (const float*)d_in[1];  // (256, 32, 512)
    const float* W_s      = (const float*)d_in[2];  // (128, 512)
    const float* W_t      = (const float*)d_in[3];  // (128, 512)
    const float* b_t      = (const float*)d_in[4];  // (128,)
    const float* v_a      = (const float*)d_in[5];  // (128, 1)
    float* out = (float*)d_out;                     // (256, 32, 256)

    (void)in_sizes; (void)n_in; (void)out_size;

    // Both projections: rows = 256*32 = 8192, cols = 128, K = 512.
    proj_kernel<<<dim3(128, 2, 2), 256>>>(dec_out, enc_outs, W_s, W_t, b_t);
    // Scores.
    score_kernel<<<dim3(SRC_LEN / 32, TRG_LEN / 32, BATCH), 256>>>(v_a, out);
}